// round 6
// baseline (speedup 1.0000x reference)
#include <cuda_runtime.h>
#include <cuda_bf16.h>
#include <cstdint>

// ---------------------------------------------------------------------------
// SimpleHOGModule: 3D gradient HOG binning.
//   input  x: (64,64,64) f32
//   output  : (1, 8, 8, 78, 78, 78) f32   (78 = 64 + 2*8 - 2)
//
// R3: quad-voxel threads on the LINEAR slice index (SLICE % 4 == 0, so every
// float4 zero-fill store is 16B-aligned independent of row wrap). Zero-fill
// is 64x STG.128 per thread (LTS-cap rate), deposits are <=3 scalar
// overwrites per voxel (same-thread program order makes overwrite safe).
// ---------------------------------------------------------------------------

#define DIN   64
#define DOUT  78
#define SLICE (78*78*78)          // 474552, divisible by 4
#define NQUAD (SLICE/4)           // 118638

__device__ __forceinline__ float ldx(const float* __restrict__ x,
                                     int z, int y, int xx) {
    if ((unsigned)z < (unsigned)DIN &&
        (unsigned)y < (unsigned)DIN &&
        (unsigned)xx < (unsigned)DIN)
        return __ldg(&x[(z * DIN + y) * DIN + xx]);
    return 0.0f;
}

__device__ __forceinline__ void voxel_bins(const float* __restrict__ x,
                                           int d, int h, int w,
                                           int& b0, int& b1, int& b2,
                                           float& w0, float& w1, float& w2) {
    const float PI_F  = 3.14159265358979323846f;
    const float EPS_F = 2.2204460492503131e-16f;

    int zc = d - 7, yc = h - 7, xc = w - 7;
    float sz = ldx(x, zc + 1, yc, xc) - ldx(x, zc - 1, yc, xc);
    float sy = ldx(x, zc, yc + 1, xc) - ldx(x, zc, yc - 1, xc);
    float sx = ldx(x, zc, yc, xc + 1) - ldx(x, zc, yc, xc - 1);

    // match reference eval order: (sz^2 + sy^2) + sx^2
    float mag = sqrtf((sz * sz + sy * sy) + sx * sx);
    float theta = atan2f(sy, sx);
    float r = sz / (mag + EPS_F);
    r = fminf(1.0f, fmaxf(-1.0f, r));   // acos-domain guard (no-op when ref finite)
    float phi = acosf(r);

    float t_raw = theta / PI_F * 8.0f;  // theta scaled by phi_bins (faithful to ref)
    float p_raw = phi   / PI_F * 8.0f;
    float t_fr = t_raw - truncf(t_raw); // torch.frac semantics
    float p_fr = p_raw - truncf(p_raw);

    int i0 = ((int)floorf(t_raw)) & 7;  // &7 == floored mod 8 (pow-2, negatives ok)
    int i1 = ((int)ceilf (t_raw)) & 7;
    int i2 = ((int)floorf(p_raw)) & 7;
    int i3 = ((int)ceilf (p_raw)) & 7;

    float f0 = fabsf(t_fr), f1 = fabsf(1.0f - t_fr);
    float f2 = fabsf(p_fr), f3 = fabsf(1.0f - p_fr);

    w0 = (f0 * f2) * mag;   // -> (i0, i2)  (scatter_ set)
    w1 = (f0 * f3) * mag;   // -> (i0, i3)  (scatter_add)
    w2 = (f1 * f2) * mag;   // -> (i1, i2)  (scatter_add)

    b0 = i0 * 8 + i2;
    b1 = i0 * 8 + i3;
    b2 = i1 * 8 + i2;

    // fold colliding deposits so each surviving bin gets exactly one store
    if (b1 == b0) w0 += w1;
    if (b2 == b0) w0 += w2;
    else if (b2 == b1) w1 += w2;
}

__global__ __launch_bounds__(256)
void hog_kernel(const float* __restrict__ x, float* __restrict__ out) {
    int q = blockIdx.x * blockDim.x + threadIdx.x;
    if (q >= NQUAD) return;

    int l = q * 4;   // linear slice index of first voxel in this quad

    int   bb0[4], bb1[4], bb2[4];
    float ww0[4], ww1[4], ww2[4];

#pragma unroll
    for (int i = 0; i < 4; i++) {
        int li = l + i;
        int w  = li % DOUT;
        int t  = li / DOUT;
        int h  = t % DOUT;
        int d  = t / DOUT;
        voxel_bins(x, d, h, w, bb0[i], bb1[i], bb2[i], ww0[i], ww1[i], ww2[i]);
    }

    float* outp = out + l;

    // dense zero fill of this quad's 64-bin column (STG.128, 16B-aligned since
    // out base is 256B-aligned and l is a multiple of 4)
    float4 z4 = make_float4(0.0f, 0.0f, 0.0f, 0.0f);
#pragma unroll
    for (int b = 0; b < 64; b++) {
        *reinterpret_cast<float4*>(outp + (size_t)b * SLICE) = z4;
    }

    // deposits — same-thread overwrites of the just-zeroed column
#pragma unroll
    for (int i = 0; i < 4; i++) {
        outp[(size_t)bb0[i] * SLICE + i] = ww0[i];
        if (bb1[i] != bb0[i])
            outp[(size_t)bb1[i] * SLICE + i] = ww1[i];
        if (bb2[i] != bb0[i] && bb2[i] != bb1[i])
            outp[(size_t)bb2[i] * SLICE + i] = ww2[i];
    }
}

extern "C" void kernel_launch(void* const* d_in, const int* in_sizes, int n_in,
                              void* d_out, int out_size) {
    const float* x = (const float*)d_in[0];   // (64,64,64) f32; weight input unused (fixed stencil)
    float* out = (float*)d_out;               // (1,8,8,78,78,78) f32

    int threads = 256;
    int blocks = (NQUAD + threads - 1) / threads;
    hog_kernel<<<blocks, threads>>>(x, out);
}